// round 4
// baseline (speedup 1.0000x reference)
#include <cuda_runtime.h>
#include <cstdint>

// Problem constants (fixed by reference setup_inputs)
#define NB    8        // batch
#define NS    4096     // source points
#define NT    16384    // target points
#define NC    8        // channels
#define NH    10       // neighbors
#define WPB   8        // warps per block
#define FULLM 0xFFFFFFFFu

typedef unsigned long long ull;

#define BUFCAP 64      // per-warp candidate buffer (worst case 22 + 32 = 54)
#define TRIG   23      // drain when count >= TRIG

// Bitonic sort of 32 u64 keys across a warp (ascending; lane k ends with k-th smallest).
__device__ __forceinline__ ull bitonic32(ull key, int lane) {
#pragma unroll
    for (int k = 2; k <= 32; k <<= 1) {
#pragma unroll
        for (int j = k >> 1; j > 0; j >>= 1) {
            ull other = __shfl_xor_sync(FULLM, key, j);
            bool up    = ((lane & k) == 0);
            bool lower = ((lane & j) == 0);
            ull mn = (key < other) ? key : other;
            ull mx = (key < other) ? other : key;
            key = (lower == up) ? mn : mx;
        }
    }
    return key;
}

// Merge buffered candidates into the distributed top-10 (lanes 0..9), refresh thr.
__device__ __forceinline__ void drain(ull& top, ull* __restrict__ buf,
                                      int& count, int lane, float& thr) {
    __syncwarp(FULLM);           // order STS pushes before LDS reads
    int cur = 0;
    while (cur < count) {
        int take = count - cur;
        if (take > 22) take = 22;
        ull v;
        if (lane < NH) {
            v = top;
        } else {
            int b = lane - NH;
            v = (b < take) ? buf[cur + b] : ~0ULL;
        }
        v = bitonic32(v, lane);
        if (lane < NH) top = v;
        cur += take;
    }
    count = 0;
    thr = __uint_as_float((unsigned)(__shfl_sync(FULLM, top, NH - 1) >> 32));
}

// Per-element push with warp-aggregated ballot; drains when buffer fills.
#define PUSH(dv, sidx)                                                        \
    {                                                                         \
        bool _c = ((dv) <= thr);                                              \
        unsigned _m = __ballot_sync(FULLM, _c);                               \
        if (_m) {                                                             \
            if (_c) buf[count + __popc(_m & ltmask)] =                        \
                (((ull)__float_as_uint(dv)) << 32) | (unsigned)(sidx);        \
            count += __popc(_m);                                              \
            if (count >= TRIG) drain(top, buf, count, lane, thr);             \
        }                                                                     \
    }

__global__ __launch_bounds__(32 * WPB, 1)
void knn_idw_kernel(const float* __restrict__ x,    // [NB, NS, NC]
                    const float* __restrict__ rel,  // [NT, NS, 2]
                    float* __restrict__ out)        // [NB, NT, NC]
{
    __shared__ ull sbuf[WPB][BUFCAP];

    const int warp = threadIdx.x >> 5;
    const int lane = threadIdx.x & 31;
    const int t    = blockIdx.x * WPB + warp;     // target index (grid covers NT)
    ull* buf = sbuf[warp];

    const float4* relrow = reinterpret_cast<const float4*>(rel + (size_t)t * NS * 2);
    const unsigned ltmask = (1u << lane) - 1u;

    // Distributed warp top-10: lane k (k<10) holds k-th smallest key.
    // key = (float_bits(d2) << 32) | source_index  -> exact order, ties by lowest idx.
    ull   top   = ~0ULL;
    float thr   = __int_as_float(0x7F800000);     // +inf: warm-up keeps all
    int   count = 0;

    // ---- Software-pipelined stream: 16 batches of 4 float4 (8 sources) per lane ----
    float4 v0 = __ldg(&relrow[lane]);
    float4 v1 = __ldg(&relrow[lane + 32]);
    float4 v2 = __ldg(&relrow[lane + 64]);
    float4 v3 = __ldg(&relrow[lane + 96]);

    for (int b = 0; b < 16; ++b) {
        const int jbase = b * 128 + lane;         // float4 index of v0 for this lane

        // Consume current batch into distances (frees v regs for prefetch).
        float d0 = v0.x * v0.x + v0.y * v0.y;
        float d1 = v0.z * v0.z + v0.w * v0.w;
        float d2 = v1.x * v1.x + v1.y * v1.y;
        float d3 = v1.z * v1.z + v1.w * v1.w;
        float d4 = v2.x * v2.x + v2.y * v2.y;
        float d5 = v2.z * v2.z + v2.w * v2.w;
        float d6 = v3.x * v3.x + v3.y * v3.y;
        float d7 = v3.z * v3.z + v3.w * v3.w;

        // Prefetch next batch BEFORE any ballot/branch -> 4 LDGs always in flight.
        if (b < 15) {
            const int nb = jbase + 128;
            v0 = __ldg(&relrow[nb]);
            v1 = __ldg(&relrow[nb + 32]);
            v2 = __ldg(&relrow[nb + 64]);
            v3 = __ldg(&relrow[nb + 96]);
        }

        // Cheap warp-coherent prefilter: one ballot per 256 warp-sources.
        float mn = fminf(fminf(fminf(d0, d1), fminf(d2, d3)),
                         fminf(fminf(d4, d5), fminf(d6, d7)));
        if (__ballot_sync(FULLM, mn <= thr)) {
            PUSH(d0, 2 * jbase);
            PUSH(d1, 2 * jbase + 1);
            PUSH(d2, 2 * (jbase + 32));
            PUSH(d3, 2 * (jbase + 32) + 1);
            PUSH(d4, 2 * (jbase + 64));
            PUSH(d5, 2 * (jbase + 64) + 1);
            PUSH(d6, 2 * (jbase + 96));
            PUSH(d7, 2 * (jbase + 96) + 1);
        }
    }
    if (count > 0) drain(top, buf, count, lane, thr);

    // ---- Weights ----
    float wk[NH];
    int   ik[NH];
    float wsum = 0.0f;
#pragma unroll
    for (int k = 0; k < NH; ++k) {
        ull kk = __shfl_sync(FULLM, top, k);
        float dd = __uint_as_float((unsigned)(kk >> 32));
        ik[k] = (int)(kk & 0xFFFFFFFFu);
        float w = 1.0f / (sqrtf(dd) + 1e-10f);
        wk[k] = w;
        wsum += w;
    }
    const float inv = 1.0f / wsum;

    // ---- Gather + weighted sum: 64 outputs (8 batch x 8 chan), 2 per lane ----
    const int b0 = lane >> 3;      // 0..3
    const int c  = lane & 7;       // 0..7
    float acc0 = 0.0f, acc1 = 0.0f;
#pragma unroll
    for (int k = 0; k < NH; ++k) {
        float w = wk[k] * inv;
        const float* xs = x + (size_t)ik[k] * NC + c;
        acc0 += w * __ldg(xs + (size_t)(b0)     * NS * NC);
        acc1 += w * __ldg(xs + (size_t)(b0 + 4) * NS * NC);
    }
    out[((size_t)(b0)     * NT + t) * NC + c] = acc0;
    out[((size_t)(b0 + 4) * NT + t) * NC + c] = acc1;
}

extern "C" void kernel_launch(void* const* d_in, const int* in_sizes, int n_in,
                              void* d_out, int out_size)
{
    const float* x   = (const float*)d_in[0];   // [8, 4096, 8]
    const float* rel = (const float*)d_in[1];   // [16384, 4096, 2]
    float* out       = (float*)d_out;           // [8, 16384, 8]
    (void)in_sizes; (void)n_in; (void)out_size;

    dim3 grid(NT / WPB);      // 2048 blocks
    dim3 block(32 * WPB);     // 256 threads
    knn_idw_kernel<<<grid, block>>>(x, rel, out);
}

// round 5
// speedup vs baseline: 1.5175x; 1.5175x over previous
#include <cuda_runtime.h>
#include <cstdint>

// Problem constants (fixed by reference setup_inputs)
#define NB    8        // batch
#define NS    4096     // source points
#define NT    16384    // target points
#define NC    8        // channels
#define NH    10       // neighbors
#define WPB   8        // warps per block
#define FULLM 0xFFFFFFFFu

typedef unsigned long long ull;

#define BUFCAP 288     // per-warp candidate buffer (worst case 22 + 256)
#define TRIG   23      // drain when count >= TRIG

// Bitonic sort of 32 u64 keys across a warp (ascending; lane k ends with k-th smallest).
__device__ __forceinline__ ull bitonic32(ull key, int lane) {
#pragma unroll
    for (int k = 2; k <= 32; k <<= 1) {
#pragma unroll
        for (int j = k >> 1; j > 0; j >>= 1) {
            ull other = __shfl_xor_sync(FULLM, key, j);
            bool up    = ((lane & k) == 0);
            bool lower = ((lane & j) == 0);
            ull mn = (key < other) ? key : other;
            ull mx = (key < other) ? other : key;
            key = (lower == up) ? mn : mx;
        }
    }
    return key;
}

// Merge buffered candidates into the distributed top-10 (lanes 0..9), refresh thr.
__device__ __noinline__ void drain(ull& top, ull* __restrict__ buf,
                                   int& count, int lane, float& thr) {
    __syncwarp(FULLM);           // order STS pushes before LDS reads
    int cur = 0;
    while (cur < count) {
        int take = count - cur;
        if (take > 22) take = 22;
        ull v;
        if (lane < NH) {
            v = top;
        } else {
            int b = lane - NH;
            v = (b < take) ? buf[cur + b] : ~0ULL;
        }
        v = bitonic32(v, lane);
        if (lane < NH) top = v;
        cur += take;
    }
    count = 0;
    thr = __uint_as_float((unsigned)(__shfl_sync(FULLM, top, NH - 1) >> 32));
    __syncwarp(FULLM);           // buf reads done before next batch overwrites
}

#define MKKEY(dv, sidx) ((((ull)__float_as_uint(dv)) << 32) | (unsigned)(sidx))

__global__ __launch_bounds__(32 * WPB, 5)
void knn_idw_kernel(const float* __restrict__ x,    // [NB, NS, NC]
                    const float* __restrict__ rel,  // [NT, NS, 2]
                    float* __restrict__ out)        // [NB, NT, NC]
{
    __shared__ ull sbuf[WPB][BUFCAP];

    const int warp = threadIdx.x >> 5;
    const int lane = threadIdx.x & 31;
    const int t    = blockIdx.x * WPB + warp;     // target index (grid covers NT)
    ull* buf = sbuf[warp];

    const float4* relrow = reinterpret_cast<const float4*>(rel + (size_t)t * NS * 2);

    // Distributed warp top-10: lane k (k<10) holds k-th smallest key.
    // key = (float_bits(d2) << 32) | source_index  -> exact order, ties by lowest idx.
    ull   top   = ~0ULL;
    float thr   = __int_as_float(0x7F800000);     // +inf until seeded in batch 0
    int   count = 0;

    // ---- Software-pipelined stream: 16 batches of 4 float4 (8 sources) per lane ----
    float4 v0 = __ldg(&relrow[lane]);
    float4 v1 = __ldg(&relrow[lane + 32]);
    float4 v2 = __ldg(&relrow[lane + 64]);
    float4 v3 = __ldg(&relrow[lane + 96]);

    for (int b = 0; b < 16; ++b) {
        const int jbase = b * 128 + lane;         // float4 index of v0 for this lane

        float d0 = v0.x * v0.x + v0.y * v0.y;
        float d1 = v0.z * v0.z + v0.w * v0.w;
        float d2 = v1.x * v1.x + v1.y * v1.y;
        float d3 = v1.z * v1.z + v1.w * v1.w;
        float d4 = v2.x * v2.x + v2.y * v2.y;
        float d5 = v2.z * v2.z + v2.w * v2.w;
        float d6 = v3.x * v3.x + v3.y * v3.y;
        float d7 = v3.z * v3.z + v3.w * v3.w;

        // Prefetch next batch BEFORE any ballot/branch -> 4 LDGs always in flight.
        if (b < 15) {
            const int nb = jbase + 128;
            v0 = __ldg(&relrow[nb]);
            v1 = __ldg(&relrow[nb + 32]);
            v2 = __ldg(&relrow[nb + 64]);
            v3 = __ldg(&relrow[nb + 96]);
        }

        float mn = fminf(fminf(fminf(d0, d1), fminf(d2, d3)),
                         fminf(fminf(d4, d5), fminf(d6, d7)));
        if (__any_sync(FULLM, mn <= thr)) {        // one ballot per 256 warp-sources
            if (b == 0) {
                // Seed thr: 10th-smallest of the 32 lane-mins (conservative & exact).
                ull mk = MKKEY(mn, lane);
                ull sorted = bitonic32(mk, lane);
                thr = __uint_as_float((unsigned)(__shfl_sync(FULLM, sorted, NH - 1) >> 32));
            }
            // Per-lane survivor flags + warp prefix-sum push (no per-element ballots).
            int c0 = d0 <= thr, c1 = d1 <= thr, c2 = d2 <= thr, c3 = d3 <= thr;
            int c4 = d4 <= thr, c5 = d5 <= thr, c6 = d6 <= thr, c7 = d7 <= thr;
            int cnt = c0 + c1 + c2 + c3 + c4 + c5 + c6 + c7;
            int scan = cnt;
#pragma unroll
            for (int s = 1; s < 32; s <<= 1) {
                int y = __shfl_up_sync(FULLM, scan, s);
                if (lane >= s) scan += y;
            }
            int total = __shfl_sync(FULLM, scan, 31);
            if (total) {
                int off = count + scan - cnt;      // exclusive start for this lane
                if (c0) buf[off++] = MKKEY(d0, 2 * jbase);
                if (c1) buf[off++] = MKKEY(d1, 2 * jbase + 1);
                if (c2) buf[off++] = MKKEY(d2, 2 * (jbase + 32));
                if (c3) buf[off++] = MKKEY(d3, 2 * (jbase + 32) + 1);
                if (c4) buf[off++] = MKKEY(d4, 2 * (jbase + 64));
                if (c5) buf[off++] = MKKEY(d5, 2 * (jbase + 64) + 1);
                if (c6) buf[off++] = MKKEY(d6, 2 * (jbase + 96));
                if (c7) buf[off++] = MKKEY(d7, 2 * (jbase + 96) + 1);
                count += total;
                if (count >= TRIG) drain(top, buf, count, lane, thr);
            }
        }
    }
    if (count > 0) drain(top, buf, count, lane, thr);

    // ---- Weights ----
    float wk[NH];
    int   ik[NH];
    float wsum = 0.0f;
#pragma unroll
    for (int k = 0; k < NH; ++k) {
        ull kk = __shfl_sync(FULLM, top, k);
        float dd = __uint_as_float((unsigned)(kk >> 32));
        ik[k] = (int)(kk & 0xFFFFFFFFu);
        float w = 1.0f / (sqrtf(dd) + 1e-10f);
        wk[k] = w;
        wsum += w;
    }
    const float inv = 1.0f / wsum;

    // ---- Gather + weighted sum: 64 outputs (8 batch x 8 chan), 2 per lane ----
    const int b0 = lane >> 3;      // 0..3
    const int c  = lane & 7;       // 0..7
    float acc0 = 0.0f, acc1 = 0.0f;
#pragma unroll
    for (int k = 0; k < NH; ++k) {
        float w = wk[k] * inv;
        const float* xs = x + (size_t)ik[k] * NC + c;
        acc0 += w * __ldg(xs + (size_t)(b0)     * NS * NC);
        acc1 += w * __ldg(xs + (size_t)(b0 + 4) * NS * NC);
    }
    out[((size_t)(b0)     * NT + t) * NC + c] = acc0;
    out[((size_t)(b0 + 4) * NT + t) * NC + c] = acc1;
}

extern "C" void kernel_launch(void* const* d_in, const int* in_sizes, int n_in,
                              void* d_out, int out_size)
{
    const float* x   = (const float*)d_in[0];   // [8, 4096, 8]
    const float* rel = (const float*)d_in[1];   // [16384, 4096, 2]
    float* out       = (float*)d_out;           // [8, 16384, 8]
    (void)in_sizes; (void)n_in; (void)out_size;

    dim3 grid(NT / WPB);      // 2048 blocks
    dim3 block(32 * WPB);     // 256 threads
    knn_idw_kernel<<<grid, block>>>(x, rel, out);
}